// round 16
// baseline (speedup 1.0000x reference)
#include <cuda_runtime.h>
#include <cuda_fp16.h>
#include <math.h>
#include <stdint.h>

// Problem constants
#define B_    4
#define N_    1024
#define DIM_  768
#define H_    12
#define KV_   4
#define D_    64
#define SIDE_ 32
#define WIN_  8
#define M_ROWS (B_ * N_)       // 4096

// Fused projection layout: [row][2560] = q(0..1535) | k(1536..2047) | v1(2048..2303) | v2(2304..2559)
#define PROJ_N 2560
#define OFF_V1 2048

// ---------------------------------------------------------------------------
// Scratch (all intermediates fp16)
// ---------------------------------------------------------------------------
__device__ __half g_xh  [M_ROWS * DIM_];
__device__ __half g_wh  [PROJ_N * DIM_];
__device__ __half g_woh [DIM_ * DIM_];
__device__ __half g_proj[M_ROWS * PROJ_N];        // fp16 projections
__device__ __half g_qkh [M_ROWS * 2048];          // fp16 roped q|k
__device__ __half g_vt  [32 * 64 * 1024];         // fp16 V transposed: [bks][d][key]
__device__ __half g_odh [2 * M_ROWS * DIM_];      // fp16 per-side normalized O (side1 pre-scaled by lambda)

// ---------------------------------------------------------------------------
// PTX helpers
// ---------------------------------------------------------------------------
__device__ __forceinline__ void mma_f16(float* c, const uint32_t* a, const uint32_t* b) {
    asm volatile(
        "mma.sync.aligned.m16n8k16.row.col.f32.f16.f16.f32 "
        "{%0,%1,%2,%3}, {%4,%5,%6,%7}, {%8,%9}, {%0,%1,%2,%3};\n"
        : "+f"(c[0]), "+f"(c[1]), "+f"(c[2]), "+f"(c[3])
        : "r"(a[0]), "r"(a[1]), "r"(a[2]), "r"(a[3]), "r"(b[0]), "r"(b[1]));
}
__device__ __forceinline__ void cpa16(void* dst, const void* src) {
    unsigned u = (unsigned)__cvta_generic_to_shared(dst);
    asm volatile("cp.async.cg.shared.global [%0], [%1], 16;\n" :: "r"(u), "l"(src));
}
__device__ __forceinline__ uint32_t h2pack(float x, float y) {
    uint32_t r;
    asm("cvt.rn.f16x2.f32 %0, %1, %2;" : "=r"(r) : "f"(y), "f"(x));
    return r;
}
// exp(x) for |x| <= 0.125: degree-4 Taylor, max rel err ~2.5e-7.
__device__ __forceinline__ float exp_small(float x) {
    float r = fmaf(x, 0.041666667f, 0.16666667f);
    r = fmaf(x, r, 0.5f);
    r = fmaf(x, r, 1.0f);
    r = fmaf(x, r, 1.0f);
    return r;
}

// ---------------------------------------------------------------------------
// Prep: convert x + concat weights to fp16.
// ---------------------------------------------------------------------------
#define PREP_TOTAL 1425408

__global__ __launch_bounds__(256)
void prep_f16(const float* __restrict__ x,  const float* __restrict__ Wq,
              const float* __restrict__ Wk, const float* __restrict__ Wv1,
              const float* __restrict__ Wv2,const float* __restrict__ Wo)
{
    int idx = blockIdx.x * 256 + threadIdx.x;
    if (idx >= PREP_TOTAL) return;

    const float4* src;
    uint2* dst;
    if (idx < 786432)        { src = (const float4*)x   + idx;           dst = (uint2*)g_xh  + idx; }
    else if (idx < 1081344)  { int i = idx - 786432;  src = (const float4*)Wq  + i; dst = (uint2*)g_wh  + i; }
    else if (idx < 1179648)  { int i = idx - 1081344; src = (const float4*)Wk  + i; dst = (uint2*)g_wh  + 294912 + i; }
    else if (idx < 1228800)  { int i = idx - 1179648; src = (const float4*)Wv1 + i; dst = (uint2*)g_wh  + 393216 + i; }
    else if (idx < 1277952)  { int i = idx - 1228800; src = (const float4*)Wv2 + i; dst = (uint2*)g_wh  + 442368 + i; }
    else                     { int i = idx - 1277952; src = (const float4*)Wo  + i; dst = (uint2*)g_woh + i; }

    float4 v = *src;
    uint2 o;
    o.x = h2pack(v.x, v.y);
    o.y = h2pack(v.z, v.w);
    *dst = o;
}

// ---------------------------------------------------------------------------
// FP16 tensor-core GEMM. If A2 != nullptr, A-operand = A - A2 (computed in
// the loader via __hsub2; used to fuse the differential combine into the Wo
// GEMM). Output: fp16 (OUTH) or fp32. 128x128 tile, TBK=64, cp.async x2 for W;
// A path uses LDG+STS when diffing, cp.async otherwise.
// ---------------------------------------------------------------------------
#define TBM 128
#define TBN 128
#define TBK 64
#define HST 72
#define GEMM_SMEM_BYTES (2 * 2 * TBM * HST * 2)   // 73728

template <bool OUTH, bool DIFF>
__global__ __launch_bounds__(256, 2)
void gemm_f16(const __half* __restrict__ A, const __half* __restrict__ A2,
              const __half* __restrict__ W,
              const float* __restrict__ bias, void* __restrict__ Cv,
              int M, int N, int K)
{
    extern __shared__ __half smh[];
    __half* As = smh;
    __half* Ws = smh + 2 * TBM * HST;

    const int tid  = threadIdx.x;
    const int lane = tid & 31;
    const int warp = tid >> 5;
    const int wm   = (warp & 1) * 64;
    const int wn   = (warp >> 1) * 32;
    const int gid  = lane >> 2;
    const int tig  = lane & 3;

    const int m0 = blockIdx.y * TBM;
    const int n0 = blockIdx.x * TBN;

    auto load_stage = [&](int st, int k0) {
#pragma unroll
        for (int i = 0; i < 4; i++) {
            int idx = tid + i * 256;          // 0..1023 : A chunks
            int r = idx >> 3;
            int c = (idx & 7) * 8;
            const __half* p1 = A + (size_t)(m0 + r) * K + k0 + c;
            if (DIFF) {
                const __half* p2 = A2 + (size_t)(m0 + r) * K + k0 + c;
                uint4 u1 = *reinterpret_cast<const uint4*>(p1);
                uint4 u2 = *reinterpret_cast<const uint4*>(p2);
                uint4 w;
                *(__half2*)&w.x = __hsub2(*(__half2*)&u1.x, *(__half2*)&u2.x);
                *(__half2*)&w.y = __hsub2(*(__half2*)&u1.y, *(__half2*)&u2.y);
                *(__half2*)&w.z = __hsub2(*(__half2*)&u1.z, *(__half2*)&u2.z);
                *(__half2*)&w.w = __hsub2(*(__half2*)&u1.w, *(__half2*)&u2.w);
                *reinterpret_cast<uint4*>(As + (st * TBM + r) * HST + c) = w;
            } else {
                cpa16(As + (st * TBM + r) * HST + c, p1);
            }
        }
#pragma unroll
        for (int i = 0; i < 4; i++) {
            int idx = tid + i * 256;
            int r = idx >> 3;
            int c = (idx & 7) * 8;
            cpa16(Ws + (st * TBN + r) * HST + c, W + (size_t)(n0 + r) * K + k0 + c);
        }
        asm volatile("cp.async.commit_group;\n" ::: "memory");
    };

    float acc[4][4][4];
#pragma unroll
    for (int i = 0; i < 4; i++)
#pragma unroll
        for (int j = 0; j < 4; j++)
#pragma unroll
            for (int l = 0; l < 4; l++) acc[i][j][l] = 0.f;

    const int nkt = K / TBK;
    load_stage(0, 0);

    for (int kt = 0; kt < nkt; kt++) {
        const int cur = kt & 1;
        if (kt + 1 < nkt) {
            load_stage(cur ^ 1, (kt + 1) * TBK);
            asm volatile("cp.async.wait_group 1;\n" ::: "memory");
        } else {
            asm volatile("cp.async.wait_group 0;\n" ::: "memory");
        }
        __syncthreads();

        const __half* Ab = As + cur * TBM * HST;
        const __half* Wb = Ws + cur * TBN * HST;

#pragma unroll
        for (int ktc = 0; ktc < 4; ktc++) {
            const int kb = ktc * 16 + 2 * tig;
            uint32_t bfr[4][2];
#pragma unroll
            for (int nt = 0; nt < 4; nt++) {
                const __half* wr = Wb + (wn + nt * 8 + gid) * HST + kb;
                bfr[nt][0] = *reinterpret_cast<const uint32_t*>(wr);
                bfr[nt][1] = *reinterpret_cast<const uint32_t*>(wr + 8);
            }
#pragma unroll
            for (int mt = 0; mt < 4; mt++) {
                const __half* ar = Ab + (wm + mt * 16 + gid) * HST + kb;
                uint32_t af[4];
                af[0] = *reinterpret_cast<const uint32_t*>(ar);
                af[1] = *reinterpret_cast<const uint32_t*>(ar + 8 * HST);
                af[2] = *reinterpret_cast<const uint32_t*>(ar + 8);
                af[3] = *reinterpret_cast<const uint32_t*>(ar + 8 * HST + 8);
#pragma unroll
                for (int nt = 0; nt < 4; nt++)
                    mma_f16(acc[mt][nt], af, bfr[nt]);
            }
        }
        __syncthreads();
    }

#pragma unroll
    for (int mt = 0; mt < 4; mt++) {
        int m = m0 + wm + mt * 16 + gid;
#pragma unroll
        for (int nt = 0; nt < 4; nt++) {
            int n = n0 + wn + nt * 8 + 2 * tig;
            float b0 = bias ? bias[n] : 0.f;
            float b1 = bias ? bias[n + 1] : 0.f;
            float c00 = acc[mt][nt][0] + b0, c01 = acc[mt][nt][1] + b1;
            float c10 = acc[mt][nt][2] + b0, c11 = acc[mt][nt][3] + b1;
            if (OUTH) {
                __half* C = (__half*)Cv;
                *reinterpret_cast<uint32_t*>(C + (size_t)m * N + n)       = h2pack(c00, c01);
                *reinterpret_cast<uint32_t*>(C + (size_t)(m + 8) * N + n) = h2pack(c10, c11);
            } else {
                float* C = (float*)Cv;
                *reinterpret_cast<float2*>(C + (size_t)m * N + n)       = make_float2(c00, c01);
                *reinterpret_cast<float2*>(C + (size_t)(m + 8) * N + n) = make_float2(c10, c11);
            }
        }
    }
}

// ---------------------------------------------------------------------------
// 2D RoPE + qk-norm. Reads fp16 g_proj q|k, computes fp32, writes fp16 g_qkh.
// ---------------------------------------------------------------------------
__global__ __launch_bounds__(256)
void rope_norm(int total_vec)
{
    const int gw   = (blockIdx.x * blockDim.x + threadIdx.x) >> 5;
    const int lane = threadIdx.x & 31;
    if (gw >= total_vec) return;

    const int row = gw >> 5;
    const int vec = gw & 31;
    const int n   = row & (N_ - 1);
    const float ph = (float)(n >> 5);
    const float pw = (float)(n & 31);

    const __half* p = g_proj + (size_t)row * PROJ_N + vec * 64;
    float x0 = __half2float(p[lane]);
    float x1 = __half2float(p[lane + 32]);

    float inv = exp2f((float)lane * -0.4152410118609203f);
    float t0 = ph * inv, t1 = pw * inv;
    float c0, s0, c1, s1;
    __sincosf(t0, &s0, &c0);
    __sincosf(t1, &s1, &c1);

    float px0 = __shfl_xor_sync(0xffffffffu, x0, 1);
    float px1 = __shfl_xor_sync(0xffffffffu, x1, 1);
    float r0 = (lane & 1) ? px0 : -px0;
    float r1 = (lane & 1) ? px1 : -px1;

    float o0 = x0 * c0 + r0 * s0;
    float o1 = x1 * c1 + r1 * s1;

    float ss = o0 * o0 + o1 * o1;
#pragma unroll
    for (int o = 16; o; o >>= 1) ss += __shfl_xor_sync(0xffffffffu, ss, o);
    float sc = 1.f / (sqrtf(ss) + 1e-6f);

    __half* q = g_qkh + (size_t)row * 2048 + vec * 64;
    q[lane]      = __float2half_rn(o0 * sc);
    q[lane + 32] = __float2half_rn(o1 * sc);
}

// ---------------------------------------------------------------------------
// V transpose: fp16 g_proj v cols -> fp16 g_vt[bks][d(64)][key(1024)].
// ---------------------------------------------------------------------------
__global__ __launch_bounds__(256)
void v_transpose()
{
    __shared__ float tile[32][65];

    const int bks    = blockIdx.x >> 5;
    const int keyblk = blockIdx.x & 31;
    const int b    = bks >> 3;
    const int kh   = (bks >> 1) & 3;
    const int side = bks & 1;
    const int col0 = OFF_V1 + side * 256 + kh * 64;
    const int tid  = threadIdx.x;

    {
        int key = tid >> 3, seg = tid & 7;
        const __half* src = g_proj + (size_t)(b * N_ + keyblk * 32 + key) * PROJ_N + col0 + seg * 8;
        uint4 raw = *reinterpret_cast<const uint4*>(src);
        const __half2* hp = reinterpret_cast<const __half2*>(&raw);
#pragma unroll
        for (int j = 0; j < 4; j++) {
            float2 f = __half22float2(hp[j]);
            tile[key][seg * 8 + 2 * j]     = f.x;
            tile[key][seg * 8 + 2 * j + 1] = f.y;
        }
    }
    __syncthreads();

    {
        int d = tid >> 2, kq = tid & 3;
        uint32_t w[4];
#pragma unroll
        for (int j = 0; j < 4; j++)
            w[j] = h2pack(tile[kq * 8 + 2 * j][d], tile[kq * 8 + 2 * j + 1][d]);
        __half* dst = g_vt + (size_t)bks * 65536 + d * 1024 + keyblk * 32 + kq * 8;
        *reinterpret_cast<uint4*>(dst) = make_uint4(w[0], w[1], w[2], w[3]);
    }
}

// ---------------------------------------------------------------------------
// fp16 tensor-core windowed attention (4 CTAs/SM).
// ---------------------------------------------------------------------------
#define KST 72
#define VST 40
#define H_STAGE (32 * KST + 64 * VST)
#define ATT_SMEM_BYTES (2 * H_STAGE * 2)

__global__ __launch_bounds__(96, 4)
void attn_tc(const float* __restrict__ lambda_p)
{
    extern __shared__ __half smh[];

    const int tid  = threadIdx.x;
    const int lane = tid & 31;
    const int warp = tid >> 5;
    const int gid  = lane >> 2;
    const int tig  = lane & 3;

    const int blk  = blockIdx.x;
    const int ph   = blk & 31;
    const int side = (blk >> 5) & 1;
    const int kh   = (blk >> 6) & 3;
    const int b    = blk >> 8;
    const int bks  = ((b * 4 + kh) * 2 + side);

    const int h = kh * 3 + warp;

    const int rlo = max(ph - WIN_, 0);
    const int rhi = min(ph + WIN_, SIDE_ - 1);
    const int nit = rhi - rlo + 1;

    const int kcol = 1536 + side * 256 + kh * 64;

    uint32_t mbits = 0;
#pragma unroll
    for (int mt = 0; mt < 2; mt++)
#pragma unroll
        for (int nt = 0; nt < 4; nt++)
#pragma unroll
            for (int c = 0; c < 4; c++) {
                int pwq = mt * 16 + gid + ((c >> 1) << 3);
                int ck  = nt * 8 + 2 * tig + (c & 1);
                int d = pwq - ck; d = (d < 0) ? -d : d;
                if (d <= WIN_) mbits |= 1u << (mt * 16 + nt * 4 + c);
            }

    auto load_stage = [&](int st, int r) {
#pragma unroll
        for (int i = 0; i < 6; i++) {
            int idx = tid + i * 96;
            if (idx < 256) {
                int key = idx >> 3, j = idx & 7;
                const __half* src = g_qkh + (size_t)(b * N_ + r * 32 + key) * 2048 + kcol + j * 8;
                cpa16(smh + st * H_STAGE + key * KST + j * 8, src);
            } else if (idx < 512) {
                int i2 = idx - 256;
                int d = i2 >> 2, j = i2 & 3;
                const __half* src = g_vt + (size_t)bks * 65536 + d * 1024 + r * 32 + j * 8;
                cpa16(smh + st * H_STAGE + 32 * KST + d * VST + j * 8, src);
            }
        }
        asm volatile("cp.async.commit_group;\n" ::: "memory");
    };

    load_stage(0, rlo);

    uint32_t qf[2][4][4];
    {
        const __half* qb = g_qkh + (size_t)(b * N_ + ph * 32) * 2048 + side * 768 + h * 64;
#pragma unroll
        for (int mt = 0; mt < 2; mt++) {
            const __half* q0 = qb + (size_t)(mt * 16 + gid) * 2048;
            const __half* q1 = q0 + (size_t)8 * 2048;
#pragma unroll
            for (int ktc = 0; ktc < 4; ktc++) {
                qf[mt][ktc][0] = *reinterpret_cast<const uint32_t*>(q0 + ktc * 16 + 2 * tig);
                qf[mt][ktc][1] = *reinterpret_cast<const uint32_t*>(q1 + ktc * 16 + 2 * tig);
                qf[mt][ktc][2] = *reinterpret_cast<const uint32_t*>(q0 + ktc * 16 + 8 + 2 * tig);
                qf[mt][ktc][3] = *reinterpret_cast<const uint32_t*>(q1 + ktc * 16 + 8 + 2 * tig);
            }
        }
    }

    float o[2][8][4];
#pragma unroll
    for (int mt = 0; mt < 2; mt++)
#pragma unroll
        for (int nt = 0; nt < 8; nt++)
#pragma unroll
            for (int c = 0; c < 4; c++) o[mt][nt][c] = 0.f;

    float l_[2][2] = {{0.f, 0.f}, {0.f, 0.f}};

    asm volatile("cp.async.wait_group 0;\n" ::: "memory");
    __syncthreads();

    for (int it = 0; it < nit; it++) {
        const int cur = it & 1;
        if (it + 1 < nit) load_stage(cur ^ 1, rlo + it + 1);

        const __half* K = smh + cur * H_STAGE;
        const __half* V = K + 32 * KST;

        float s[2][4][4];
#pragma unroll
        for (int mt = 0; mt < 2; mt++)
#pragma unroll
            for (int nt = 0; nt < 4; nt++)
#pragma unroll
                for (int c = 0; c < 4; c++) s[mt][nt][c] = 0.f;

#pragma unroll
        for (int ktc = 0; ktc < 4; ktc++) {
            uint32_t bf[4][2];
#pragma unroll
            for (int nt = 0; nt < 4; nt++) {
                const __half* kr = K + (nt * 8 + gid) * KST + ktc * 16 + 2 * tig;
                bf[nt][0] = *reinterpret_cast<const uint32_t*>(kr);
                bf[nt][1] = *reinterpret_cast<const uint32_t*>(kr + 8);
            }
#pragma unroll
            for (int mt = 0; mt < 2; mt++)
#pragma unroll
                for (int nt = 0; nt < 4; nt++) {
                    if ((mt == 0 && nt == 3) || (mt == 1 && nt == 0)) continue;
                    mma_f16(s[mt][nt], qf[mt][ktc], bf[nt]);
                }
        }

        uint32_t paf[2][2][4];
#pragma unroll
        for (int mt = 0; mt < 2; mt++)
#pragma unroll
            for (int k2 = 0; k2 < 2; k2++)
#pragma unroll
                for (int q = 0; q < 4; q++) paf[mt][k2][q] = 0;

#pragma unroll
        for (int mt = 0; mt < 2; mt++)
#pragma unroll
            for (int nt = 0; nt < 4; nt++) {
                if ((mt == 0 && nt == 3) || (mt == 1 && nt == 0)) continue;
                float p0 = exp_small(s[mt][nt][0] * 0.125f);
                float p1 = exp_small(s[mt][nt][1] * 0.125f);
                float p2 = exp_small(s[mt][nt][2] * 0.125f);
                float p3 = exp_small(s[mt][nt][3] * 0.125f);
                p0 = (mbits >> (mt * 16 + nt * 4 + 0)) & 1 ? p0 : 0.f;
                p1 = (mbits >> (mt * 16 + nt * 4 + 1)) & 1 ? p1 : 0.f;
                p2 = (mbits >> (mt * 16 + nt * 4 + 2)) & 1 ? p2 : 0.f;
                p3 = (mbits >> (mt * 16 + nt * 4 + 3)) & 1 ? p3 : 0.f;
                l_[mt][0] += p0 + p1;
                l_[mt][1] += p2 + p3;
                paf[mt][nt >> 1][(nt & 1) * 2 + 0] = h2pack(p0, p1);
                paf[mt][nt >> 1][(nt & 1) * 2 + 1] = h2pack(p2, p3);
            }

#pragma unroll
        for (int k2 = 0; k2 < 2; k2++) {
#pragma unroll
            for (int nt = 0; nt < 8; nt++) {
                const __half* vr = V + (nt * 8 + gid) * VST + k2 * 16 + 2 * tig;
                uint32_t bf[2];
                bf[0] = *reinterpret_cast<const uint32_t*>(vr);
                bf[1] = *reinterpret_cast<const uint32_t*>(vr + 8);
                mma_f16(o[0][nt], paf[0][k2], bf);
                mma_f16(o[1][nt], paf[1][k2], bf);
            }
        }

        asm volatile("cp.async.wait_group 0;\n" ::: "memory");
        __syncthreads();
    }

#pragma unroll
    for (int mt = 0; mt < 2; mt++)
#pragma unroll
        for (int hf = 0; hf < 2; hf++) {
            float r = l_[mt][hf];
            r += __shfl_xor_sync(0xffffffffu, r, 1);
            r += __shfl_xor_sync(0xffffffffu, r, 2);
            l_[mt][hf] = r;
        }

    float lam = side ? log1pf(__expf(lambda_p[h])) : 1.f;
    float inv[2][2] = {{lam / l_[0][0], lam / l_[0][1]},
                       {lam / l_[1][0], lam / l_[1][1]}};

    __half* dst = g_odh + ((size_t)side * M_ROWS + (size_t)(b * N_ + ph * 32)) * 768 + h * 64;
#pragma unroll
    for (int mt = 0; mt < 2; mt++)
#pragma unroll
        for (int nt = 0; nt < 8; nt++) {
            int r0 = mt * 16 + gid, r1 = r0 + 8, cc = nt * 8 + 2 * tig;
            *reinterpret_cast<uint32_t*>(dst + (size_t)r0 * 768 + cc) =
                h2pack(o[mt][nt][0] * inv[mt][0], o[mt][nt][1] * inv[mt][0]);
            *reinterpret_cast<uint32_t*>(dst + (size_t)r1 * 768 + cc) =
                h2pack(o[mt][nt][2] * inv[mt][1], o[mt][nt][3] * inv[mt][1]);
        }
}

// ---------------------------------------------------------------------------
// Launch
// ---------------------------------------------------------------------------
extern "C" void kernel_launch(void* const* d_in, const int* in_sizes, int n_in,
                              void* d_out, int out_size)
{
    const float* x      = (const float*)d_in[0];
    const float* Wq     = (const float*)d_in[1];
    const float* Wk     = (const float*)d_in[2];
    const float* Wv1    = (const float*)d_in[3];
    const float* Wv2    = (const float*)d_in[4];
    const float* lam_p  = (const float*)d_in[5];
    const float* Wo     = (const float*)d_in[6];
    const float* bo     = (const float*)d_in[7];
    float* out = (float*)d_out;

    __half *gxh, *gwh, *gwoh, *proj, *odh;
    cudaGetSymbolAddress((void**)&gxh,  g_xh);
    cudaGetSymbolAddress((void**)&gwh,  g_wh);
    cudaGetSymbolAddress((void**)&gwoh, g_woh);
    cudaGetSymbolAddress((void**)&proj, g_proj);
    cudaGetSymbolAddress((void**)&odh,  g_odh);

    cudaFuncSetAttribute((const void*)gemm_f16<true,  false>, cudaFuncAttributeMaxDynamicSharedMemorySize, GEMM_SMEM_BYTES);
    cudaFuncSetAttribute((const void*)gemm_f16<false, true >, cudaFuncAttributeMaxDynamicSharedMemorySize, GEMM_SMEM_BYTES);
    cudaFuncSetAttribute(attn_tc, cudaFuncAttributeMaxDynamicSharedMemorySize, ATT_SMEM_BYTES);
    cudaFuncSetAttribute(attn_tc, cudaFuncAttributePreferredSharedMemoryCarveout, 100);

    // fp16 conversion + weight concat
    prep_f16<<<(PREP_TOTAL + 255) / 256, 256>>>(x, Wq, Wk, Wv1, Wv2, Wo);

    // fused projections: fp16 GEMM [4096 x 2560 x 768] -> fp16 g_proj
    gemm_f16<true, false><<<dim3(PROJ_N / TBN, M_ROWS / TBM), 256, GEMM_SMEM_BYTES>>>(
        gxh, nullptr, gwh, nullptr, proj, M_ROWS, PROJ_N, DIM_);

    // RoPE + qk-norm -> fp16 g_qkh
    {
        int vec = M_ROWS * 32;
        rope_norm<<<(vec * 32 + 255) / 256, 256>>>(vec);
    }

    // V transpose -> g_vt
    v_transpose<<<1024, 256>>>();

    // fp16 tensor-core windowed attention -> fp16 g_odh (side1 lambda-scaled)
    attn_tc<<<B_ * KV_ * 2 * SIDE_, 96, ATT_SMEM_BYTES>>>(lam_p);

    // output projection: A = (O1 - O2) computed inline in the loader
    gemm_f16<false, true><<<dim3(DIM_ / TBN, M_ROWS / TBM), 256, GEMM_SMEM_BYTES>>>(
        odh, odh + (size_t)M_ROWS * DIM_, gwoh, bo, out, M_ROWS, DIM_, DIM_);
}

// round 17
// speedup vs baseline: 1.0201x; 1.0201x over previous
#include <cuda_runtime.h>
#include <cuda_fp16.h>
#include <math.h>
#include <stdint.h>

// Problem constants
#define B_    4
#define N_    1024
#define DIM_  768
#define H_    12
#define KV_   4
#define D_    64
#define SIDE_ 32
#define WIN_  8
#define M_ROWS (B_ * N_)       // 4096

// Fused projection layout: [row][2560] = q(0..1535) | k(1536..2047) | v1(2048..2303) | v2(2304..2559)
#define PROJ_N 2560
#define OFF_V1 2048

// ---------------------------------------------------------------------------
// Scratch (all intermediates fp16)
// ---------------------------------------------------------------------------
__device__ __half g_xh  [M_ROWS * DIM_];
__device__ __half g_wh  [PROJ_N * DIM_];
__device__ __half g_woh [DIM_ * DIM_];
__device__ __half g_proj[M_ROWS * PROJ_N];
__device__ __half g_qkh [M_ROWS * 2048];
__device__ __half g_vt  [32 * 64 * 1024];         // [bks][d][key]
__device__ __half g_odh [2 * M_ROWS * DIM_];      // per-side normalized O (side1 lambda-scaled)
__device__ __half g_ctxh[M_ROWS * DIM_];

// ---------------------------------------------------------------------------
// PTX helpers
// ---------------------------------------------------------------------------
__device__ __forceinline__ void mma_f16(float* c, const uint32_t* a, const uint32_t* b) {
    asm volatile(
        "mma.sync.aligned.m16n8k16.row.col.f32.f16.f16.f32 "
        "{%0,%1,%2,%3}, {%4,%5,%6,%7}, {%8,%9}, {%0,%1,%2,%3};\n"
        : "+f"(c[0]), "+f"(c[1]), "+f"(c[2]), "+f"(c[3])
        : "r"(a[0]), "r"(a[1]), "r"(a[2]), "r"(a[3]), "r"(b[0]), "r"(b[1]));
}
__device__ __forceinline__ void cpa16(void* dst, const void* src) {
    unsigned u = (unsigned)__cvta_generic_to_shared(dst);
    asm volatile("cp.async.cg.shared.global [%0], [%1], 16;\n" :: "r"(u), "l"(src));
}
__device__ __forceinline__ uint32_t h2pack(float x, float y) {
    uint32_t r;
    asm("cvt.rn.f16x2.f32 %0, %1, %2;" : "=r"(r) : "f"(y), "f"(x));
    return r;
}
// exp(x) for |x| <= 0.125: degree-4 Taylor, max rel err ~2.5e-7.
__device__ __forceinline__ float exp_small(float x) {
    float r = fmaf(x, 0.041666667f, 0.16666667f);
    r = fmaf(x, r, 0.5f);
    r = fmaf(x, r, 1.0f);
    r = fmaf(x, r, 1.0f);
    return r;
}

// ---------------------------------------------------------------------------
// Prep: convert x + concat weights to fp16.
// ---------------------------------------------------------------------------
#define PREP_TOTAL 1425408

__global__ __launch_bounds__(256)
void prep_f16(const float* __restrict__ x,  const float* __restrict__ Wq,
              const float* __restrict__ Wk, const float* __restrict__ Wv1,
              const float* __restrict__ Wv2,const float* __restrict__ Wo)
{
    int idx = blockIdx.x * 256 + threadIdx.x;
    if (idx >= PREP_TOTAL) return;

    const float4* src;
    uint2* dst;
    if (idx < 786432)        { src = (const float4*)x   + idx;           dst = (uint2*)g_xh  + idx; }
    else if (idx < 1081344)  { int i = idx - 786432;  src = (const float4*)Wq  + i; dst = (uint2*)g_wh  + i; }
    else if (idx < 1179648)  { int i = idx - 1081344; src = (const float4*)Wk  + i; dst = (uint2*)g_wh  + 294912 + i; }
    else if (idx < 1228800)  { int i = idx - 1179648; src = (const float4*)Wv1 + i; dst = (uint2*)g_wh  + 393216 + i; }
    else if (idx < 1277952)  { int i = idx - 1228800; src = (const float4*)Wv2 + i; dst = (uint2*)g_wh  + 442368 + i; }
    else                     { int i = idx - 1277952; src = (const float4*)Wo  + i; dst = (uint2*)g_woh + i; }

    float4 v = *src;
    uint2 o;
    o.x = h2pack(v.x, v.y);
    o.y = h2pack(v.z, v.w);
    *dst = o;
}

// ---------------------------------------------------------------------------
// FP16 tensor-core GEMM (round-15 version): acc fp32; out fp16 or fp32.
// 128x128 tile, TBK=64, 8 warps (2x4), 64x32 warp tile, cp.async x2.
// ---------------------------------------------------------------------------
#define TBM 128
#define TBN 128
#define TBK 64
#define HST 72
#define GEMM_SMEM_BYTES (2 * 2 * TBM * HST * 2)   // 73728

template <bool OUTH>
__global__ __launch_bounds__(256, 2)
void gemm_f16(const __half* __restrict__ A, const __half* __restrict__ W,
              const float* __restrict__ bias, void* __restrict__ Cv,
              int M, int N, int K)
{
    extern __shared__ __half smh[];
    __half* As = smh;
    __half* Ws = smh + 2 * TBM * HST;

    const int tid  = threadIdx.x;
    const int lane = tid & 31;
    const int warp = tid >> 5;
    const int wm   = (warp & 1) * 64;
    const int wn   = (warp >> 1) * 32;
    const int gid  = lane >> 2;
    const int tig  = lane & 3;

    const int m0 = blockIdx.y * TBM;
    const int n0 = blockIdx.x * TBN;

    auto load_stage = [&](int st, int k0) {
#pragma unroll
        for (int i = 0; i < 8; i++) {
            int idx = tid + i * 256;
            int r = (idx & 1023) >> 3;
            int c = (idx & 7) * 8;
            if (idx < 1024)
                cpa16(As + (st * TBM + r) * HST + c, A + (size_t)(m0 + r) * K + k0 + c);
            else
                cpa16(Ws + (st * TBN + r) * HST + c, W + (size_t)(n0 + r) * K + k0 + c);
        }
        asm volatile("cp.async.commit_group;\n" ::: "memory");
    };

    float acc[4][4][4];
#pragma unroll
    for (int i = 0; i < 4; i++)
#pragma unroll
        for (int j = 0; j < 4; j++)
#pragma unroll
            for (int l = 0; l < 4; l++) acc[i][j][l] = 0.f;

    const int nkt = K / TBK;
    load_stage(0, 0);

    for (int kt = 0; kt < nkt; kt++) {
        const int cur = kt & 1;
        if (kt + 1 < nkt) {
            load_stage(cur ^ 1, (kt + 1) * TBK);
            asm volatile("cp.async.wait_group 1;\n" ::: "memory");
        } else {
            asm volatile("cp.async.wait_group 0;\n" ::: "memory");
        }
        __syncthreads();

        const __half* Ab = As + cur * TBM * HST;
        const __half* Wb = Ws + cur * TBN * HST;

#pragma unroll
        for (int ktc = 0; ktc < 4; ktc++) {
            const int kb = ktc * 16 + 2 * tig;
            uint32_t bfr[4][2];
#pragma unroll
            for (int nt = 0; nt < 4; nt++) {
                const __half* wr = Wb + (wn + nt * 8 + gid) * HST + kb;
                bfr[nt][0] = *reinterpret_cast<const uint32_t*>(wr);
                bfr[nt][1] = *reinterpret_cast<const uint32_t*>(wr + 8);
            }
#pragma unroll
            for (int mt = 0; mt < 4; mt++) {
                const __half* ar = Ab + (wm + mt * 16 + gid) * HST + kb;
                uint32_t af[4];
                af[0] = *reinterpret_cast<const uint32_t*>(ar);
                af[1] = *reinterpret_cast<const uint32_t*>(ar + 8 * HST);
                af[2] = *reinterpret_cast<const uint32_t*>(ar + 8);
                af[3] = *reinterpret_cast<const uint32_t*>(ar + 8 * HST + 8);
#pragma unroll
                for (int nt = 0; nt < 4; nt++)
                    mma_f16(acc[mt][nt], af, bfr[nt]);
            }
        }
        __syncthreads();
    }

#pragma unroll
    for (int mt = 0; mt < 4; mt++) {
        int m = m0 + wm + mt * 16 + gid;
#pragma unroll
        for (int nt = 0; nt < 4; nt++) {
            int n = n0 + wn + nt * 8 + 2 * tig;
            float b0 = bias ? bias[n] : 0.f;
            float b1 = bias ? bias[n + 1] : 0.f;
            float c00 = acc[mt][nt][0] + b0, c01 = acc[mt][nt][1] + b1;
            float c10 = acc[mt][nt][2] + b0, c11 = acc[mt][nt][3] + b1;
            if (OUTH) {
                __half* C = (__half*)Cv;
                *reinterpret_cast<uint32_t*>(C + (size_t)m * N + n)       = h2pack(c00, c01);
                *reinterpret_cast<uint32_t*>(C + (size_t)(m + 8) * N + n) = h2pack(c10, c11);
            } else {
                float* C = (float*)Cv;
                *reinterpret_cast<float2*>(C + (size_t)m * N + n)       = make_float2(c00, c01);
                *reinterpret_cast<float2*>(C + (size_t)(m + 8) * N + n) = make_float2(c10, c11);
            }
        }
    }
}

// ---------------------------------------------------------------------------
// 2D RoPE + qk-norm (round-15 version).
// ---------------------------------------------------------------------------
__global__ __launch_bounds__(256)
void rope_norm(int total_vec)
{
    const int gw   = (blockIdx.x * blockDim.x + threadIdx.x) >> 5;
    const int lane = threadIdx.x & 31;
    if (gw >= total_vec) return;

    const int row = gw >> 5;
    const int vec = gw & 31;
    const int n   = row & (N_ - 1);
    const float ph = (float)(n >> 5);
    const float pw = (float)(n & 31);

    const __half* p = g_proj + (size_t)row * PROJ_N + vec * 64;
    float x0 = __half2float(p[lane]);
    float x1 = __half2float(p[lane + 32]);

    float inv = exp2f((float)lane * -0.4152410118609203f);
    float t0 = ph * inv, t1 = pw * inv;
    float c0, s0, c1, s1;
    __sincosf(t0, &s0, &c0);
    __sincosf(t1, &s1, &c1);

    float px0 = __shfl_xor_sync(0xffffffffu, x0, 1);
    float px1 = __shfl_xor_sync(0xffffffffu, x1, 1);
    float r0 = (lane & 1) ? px0 : -px0;
    float r1 = (lane & 1) ? px1 : -px1;

    float o0 = x0 * c0 + r0 * s0;
    float o1 = x1 * c1 + r1 * s1;

    float ss = o0 * o0 + o1 * o1;
#pragma unroll
    for (int o = 16; o; o >>= 1) ss += __shfl_xor_sync(0xffffffffu, ss, o);
    float sc = 1.f / (sqrtf(ss) + 1e-6f);

    __half* q = g_qkh + (size_t)row * 2048 + vec * 64;
    q[lane]      = __float2half_rn(o0 * sc);
    q[lane + 32] = __float2half_rn(o1 * sc);
}

// ---------------------------------------------------------------------------
// V transpose (round-15 version).
// ---------------------------------------------------------------------------
__global__ __launch_bounds__(256)
void v_transpose()
{
    __shared__ float tile[32][65];

    const int bks    = blockIdx.x >> 5;
    const int keyblk = blockIdx.x & 31;
    const int b    = bks >> 3;
    const int kh   = (bks >> 1) & 3;
    const int side = bks & 1;
    const int col0 = OFF_V1 + side * 256 + kh * 64;
    const int tid  = threadIdx.x;

    {
        int key = tid >> 3, seg = tid & 7;
        const __half* src = g_proj + (size_t)(b * N_ + keyblk * 32 + key) * PROJ_N + col0 + seg * 8;
        uint4 raw = *reinterpret_cast<const uint4*>(src);
        const __half2* hp = reinterpret_cast<const __half2*>(&raw);
#pragma unroll
        for (int j = 0; j < 4; j++) {
            float2 f = __half22float2(hp[j]);
            tile[key][seg * 8 + 2 * j]     = f.x;
            tile[key][seg * 8 + 2 * j + 1] = f.y;
        }
    }
    __syncthreads();

    {
        int d = tid >> 2, kq = tid & 3;
        uint32_t w[4];
#pragma unroll
        for (int j = 0; j < 4; j++)
            w[j] = h2pack(tile[kq * 8 + 2 * j][d], tile[kq * 8 + 2 * j + 1][d]);
        __half* dst = g_vt + (size_t)bks * 65536 + d * 1024 + keyblk * 32 + kq * 8;
        *reinterpret_cast<uint4*>(dst) = make_uint4(w[0], w[1], w[2], w[3]);
    }
}

// ---------------------------------------------------------------------------
// fp16 tensor-core windowed attention, PH-PAIR blocks.
// Block = (b, kh, side, php): 512 blocks, 6 warps (192 thr).
// Warp = (head hloc, ph-half qh): ph_w = 2*php + qh. All warps iterate the
// UNION window [2php-8, 2php+9] clipped; a warp skips compute for key rows
// outside its own [ph_w-8, ph_w+8] (exact-zero contributions anyway).
// KV staging traffic halves vs per-ph blocks.
// ---------------------------------------------------------------------------
#define KST 72
#define VST 40
#define H_STAGE (32 * KST + 64 * VST)
#define ATT_SMEM_BYTES (2 * H_STAGE * 2)

__global__ __launch_bounds__(192, 2)
void attn_tc(const float* __restrict__ lambda_p)
{
    extern __shared__ __half smh[];

    const int tid  = threadIdx.x;
    const int lane = tid & 31;
    const int warp = tid >> 5;           // 0..5
    const int gid  = lane >> 2;
    const int tig  = lane & 3;

    const int blk  = blockIdx.x;         // b(4) x kh(4) x side(2) x php(16)
    const int php  = blk & 15;
    const int side = (blk >> 4) & 1;
    const int kh   = (blk >> 5) & 3;
    const int b    = blk >> 7;
    const int bks  = ((b * 4 + kh) * 2 + side);

    const int qh   = warp & 1;           // ph-half
    const int hloc = warp >> 1;          // 0..2
    const int h    = kh * 3 + hloc;
    const int ph_w = php * 2 + qh;

    const int rlo_b = max(php * 2 - WIN_, 0);
    const int rhi_b = min(php * 2 + 1 + WIN_, SIDE_ - 1);
    const int nit   = rhi_b - rlo_b + 1;
    const int rlo_w = max(ph_w - WIN_, 0);
    const int rhi_w = min(ph_w + WIN_, SIDE_ - 1);

    const int kcol = 1536 + side * 256 + kh * 64;

    // column mask: bit (mt*16 + nt*4 + c) = |pwq - ck| <= WIN
    uint32_t mbits = 0;
#pragma unroll
    for (int mt = 0; mt < 2; mt++)
#pragma unroll
        for (int nt = 0; nt < 4; nt++)
#pragma unroll
            for (int c = 0; c < 4; c++) {
                int pwq = mt * 16 + gid + ((c >> 1) << 3);
                int ck  = nt * 8 + 2 * tig + (c & 1);
                int d = pwq - ck; d = (d < 0) ? -d : d;
                if (d <= WIN_) mbits |= 1u << (mt * 16 + nt * 4 + c);
            }

    // loader: 512 chunks over 192 threads (K 256 + Vt 256)
    auto load_stage = [&](int st, int r) {
#pragma unroll
        for (int i = 0; i < 3; i++) {
            int idx = tid + i * 192;
            if (idx < 256) {
                int key = idx >> 3, j = idx & 7;
                const __half* src = g_qkh + (size_t)(b * N_ + r * 32 + key) * 2048 + kcol + j * 8;
                cpa16(smh + st * H_STAGE + key * KST + j * 8, src);
            } else if (idx < 512) {
                int i2 = idx - 256;
                int d = i2 >> 2, j = i2 & 3;
                const __half* src = g_vt + (size_t)bks * 65536 + d * 1024 + r * 32 + j * 8;
                cpa16(smh + st * H_STAGE + 32 * KST + d * VST + j * 8, src);
            }
        }
        asm volatile("cp.async.commit_group;\n" ::: "memory");
    };

    load_stage(0, rlo_b);

    // Q A-fragments (fp16)
    uint32_t qf[2][4][4];
    {
        const __half* qb = g_qkh + (size_t)(b * N_ + ph_w * 32) * 2048 + side * 768 + h * 64;
#pragma unroll
        for (int mt = 0; mt < 2; mt++) {
            const __half* q0 = qb + (size_t)(mt * 16 + gid) * 2048;
            const __half* q1 = q0 + (size_t)8 * 2048;
#pragma unroll
            for (int ktc = 0; ktc < 4; ktc++) {
                qf[mt][ktc][0] = *reinterpret_cast<const uint32_t*>(q0 + ktc * 16 + 2 * tig);
                qf[mt][ktc][1] = *reinterpret_cast<const uint32_t*>(q1 + ktc * 16 + 2 * tig);
                qf[mt][ktc][2] = *reinterpret_cast<const uint32_t*>(q0 + ktc * 16 + 8 + 2 * tig);
                qf[mt][ktc][3] = *reinterpret_cast<const uint32_t*>(q1 + ktc * 16 + 8 + 2 * tig);
            }
        }
    }

    float o[2][8][4];
#pragma unroll
    for (int mt = 0; mt < 2; mt++)
#pragma unroll
        for (int nt = 0; nt < 8; nt++)
#pragma unroll
            for (int c = 0; c < 4; c++) o[mt][nt][c] = 0.f;

    float l_[2][2] = {{0.f, 0.f}, {0.f, 0.f}};

    asm volatile("cp.async.wait_group 0;\n" ::: "memory");
    __syncthreads();

    for (int it = 0; it < nit; it++) {
        const int cur = it & 1;
        const int r = rlo_b + it;
        if (it + 1 < nit) load_stage(cur ^ 1, r + 1);

        const bool rvalid = (r >= rlo_w) && (r <= rhi_w);
        if (rvalid) {
            const __half* K = smh + cur * H_STAGE;
            const __half* V = K + 32 * KST;

            // ---- S = Q @ K^T (skip dead (0,3),(1,0))
            float s[2][4][4];
#pragma unroll
            for (int mt = 0; mt < 2; mt++)
#pragma unroll
                for (int nt = 0; nt < 4; nt++)
#pragma unroll
                    for (int c = 0; c < 4; c++) s[mt][nt][c] = 0.f;

#pragma unroll
            for (int ktc = 0; ktc < 4; ktc++) {
                uint32_t bf[4][2];
#pragma unroll
                for (int nt = 0; nt < 4; nt++) {
                    const __half* kr = K + (nt * 8 + gid) * KST + ktc * 16 + 2 * tig;
                    bf[nt][0] = *reinterpret_cast<const uint32_t*>(kr);
                    bf[nt][1] = *reinterpret_cast<const uint32_t*>(kr + 8);
                }
#pragma unroll
                for (int mt = 0; mt < 2; mt++)
#pragma unroll
                    for (int nt = 0; nt < 4; nt++) {
                        if ((mt == 0 && nt == 3) || (mt == 1 && nt == 0)) continue;
                        mma_f16(s[mt][nt], qf[mt][ktc], bf[nt]);
                    }
            }

            // ---- exp + mask + pack to fp16 A-fragments
            uint32_t paf[2][2][4];
#pragma unroll
            for (int mt = 0; mt < 2; mt++)
#pragma unroll
                for (int k2 = 0; k2 < 2; k2++)
#pragma unroll
                    for (int q = 0; q < 4; q++) paf[mt][k2][q] = 0;

#pragma unroll
            for (int mt = 0; mt < 2; mt++)
#pragma unroll
                for (int nt = 0; nt < 4; nt++) {
                    if ((mt == 0 && nt == 3) || (mt == 1 && nt == 0)) continue;
                    float p0 = exp_small(s[mt][nt][0] * 0.125f);
                    float p1 = exp_small(s[mt][nt][1] * 0.125f);
                    float p2 = exp_small(s[mt][nt][2] * 0.125f);
                    float p3 = exp_small(s[mt][nt][3] * 0.125f);
                    p0 = (mbits >> (mt * 16 + nt * 4 + 0)) & 1 ? p0 : 0.f;
                    p1 = (mbits >> (mt * 16 + nt * 4 + 1)) & 1 ? p1 : 0.f;
                    p2 = (mbits >> (mt * 16 + nt * 4 + 2)) & 1 ? p2 : 0.f;
                    p3 = (mbits >> (mt * 16 + nt * 4 + 3)) & 1 ? p3 : 0.f;
                    l_[mt][0] += p0 + p1;
                    l_[mt][1] += p2 + p3;
                    paf[mt][nt >> 1][(nt & 1) * 2 + 0] = h2pack(p0, p1);
                    paf[mt][nt >> 1][(nt & 1) * 2 + 1] = h2pack(p2, p3);
                }

            // ---- O += P @ V
#pragma unroll
            for (int k2 = 0; k2 < 2; k2++) {
#pragma unroll
                for (int nt = 0; nt < 8; nt++) {
                    const __half* vr = V + (nt * 8 + gid) * VST + k2 * 16 + 2 * tig;
                    uint32_t bf[2];
                    bf[0] = *reinterpret_cast<const uint32_t*>(vr);
                    bf[1] = *reinterpret_cast<const uint32_t*>(vr + 8);
                    mma_f16(o[0][nt], paf[0][k2], bf);
                    mma_f16(o[1][nt], paf[1][k2], bf);
                }
            }
        }

        asm volatile("cp.async.wait_group 0;\n" ::: "memory");
        __syncthreads();
    }

    // ---- final row-sum reduction
#pragma unroll
    for (int mt = 0; mt < 2; mt++)
#pragma unroll
        for (int hf = 0; hf < 2; hf++) {
            float r = l_[mt][hf];
            r += __shfl_xor_sync(0xffffffffu, r, 1);
            r += __shfl_xor_sync(0xffffffffu, r, 2);
            l_[mt][hf] = r;
        }

    float lam = side ? log1pf(__expf(lambda_p[h])) : 1.f;
    float inv[2][2] = {{lam / l_[0][0], lam / l_[0][1]},
                       {lam / l_[1][0], lam / l_[1][1]}};

    __half* dst = g_odh + ((size_t)side * M_ROWS + (size_t)(b * N_ + ph_w * 32)) * 768 + h * 64;
#pragma unroll
    for (int mt = 0; mt < 2; mt++)
#pragma unroll
        for (int nt = 0; nt < 8; nt++) {
            int r0 = mt * 16 + gid, r1 = r0 + 8, cc = nt * 8 + 2 * tig;
            *reinterpret_cast<uint32_t*>(dst + (size_t)r0 * 768 + cc) =
                h2pack(o[mt][nt][0] * inv[mt][0], o[mt][nt][1] * inv[mt][0]);
            *reinterpret_cast<uint32_t*>(dst + (size_t)r1 * 768 + cc) =
                h2pack(o[mt][nt][2] * inv[mt][1], o[mt][nt][3] * inv[mt][1]);
        }
}

// ---------------------------------------------------------------------------
// Combine: ctxh = fp16(O1 - O2_scaled). (round-15 version)
// ---------------------------------------------------------------------------
#define CTX_Q (M_ROWS * DIM_ / 4)   // 786432

__global__ __launch_bounds__(256)
void combine_o()
{
    int idx = blockIdx.x * 256 + threadIdx.x;
    if (idx >= CTX_Q) return;
    uint2 a = reinterpret_cast<const uint2*>(g_odh)[idx];
    uint2 c = reinterpret_cast<const uint2*>(g_odh + (size_t)M_ROWS * DIM_)[idx];
    float2 a0 = __half22float2(*reinterpret_cast<__half2*>(&a.x));
    float2 a1 = __half22float2(*reinterpret_cast<__half2*>(&a.y));
    float2 c0 = __half22float2(*reinterpret_cast<__half2*>(&c.x));
    float2 c1 = __half22float2(*reinterpret_cast<__half2*>(&c.y));
    uint2 r;
    r.x = h2pack(a0.x - c0.x, a0.y - c0.y);
    r.y = h2pack(a1.x - c1.x, a1.y - c1.y);
    reinterpret_cast<uint2*>(g_ctxh)[idx] = r;
}

// ---------------------------------------------------------------------------
// Launch
// ---------------------------------------------------------------------------
extern "C" void kernel_launch(void* const* d_in, const int* in_sizes, int n_in,
                              void* d_out, int out_size)
{
    const float* x      = (const float*)d_in[0];
    const float* Wq     = (const float*)d_in[1];
    const float* Wk     = (const float*)d_in[2];
    const float* Wv1    = (const float*)d_in[3];
    const float* Wv2    = (const float*)d_in[4];
    const float* lam_p  = (const float*)d_in[5];
    const float* Wo     = (const float*)d_in[6];
    const float* bo     = (const float*)d_in[7];
    float* out = (float*)d_out;

    __half *gxh, *gwh, *gwoh, *proj, *ctxh;
    cudaGetSymbolAddress((void**)&gxh,  g_xh);
    cudaGetSymbolAddress((void**)&gwh,  g_wh);
    cudaGetSymbolAddress((void**)&gwoh, g_woh);
    cudaGetSymbolAddress((void**)&proj, g_proj);
    cudaGetSymbolAddress((void**)&ctxh, g_ctxh);

    cudaFuncSetAttribute(gemm_f16<true>,  cudaFuncAttributeMaxDynamicSharedMemorySize, GEMM_SMEM_BYTES);
    cudaFuncSetAttribute(gemm_f16<false>, cudaFuncAttributeMaxDynamicSharedMemorySize, GEMM_SMEM_BYTES);
    cudaFuncSetAttribute(attn_tc, cudaFuncAttributeMaxDynamicSharedMemorySize, ATT_SMEM_BYTES);

    // fp16 conversion + weight concat
    prep_f16<<<(PREP_TOTAL + 255) / 256, 256>>>(x, Wq, Wk, Wv1, Wv2, Wo);

    // fused projections: fp16 GEMM [4096 x 2560 x 768] -> fp16 g_proj
    gemm_f16<true><<<dim3(PROJ_N / TBN, M_ROWS / TBM), 256, GEMM_SMEM_BYTES>>>(
        gxh, gwh, nullptr, proj, M_ROWS, PROJ_N, DIM_);

    // RoPE + qk-norm -> fp16 g_qkh
    {
        int vec = M_ROWS * 32;
        rope_norm<<<(vec * 32 + 255) / 256, 256>>>(vec);
    }

    // V transpose -> g_vt
    v_transpose<<<1024, 256>>>();

    // fp16 tensor-core windowed attention (ph-pair blocks) -> fp16 g_odh
    attn_tc<<<B_ * KV_ * 2 * 16, 192, ATT_SMEM_BYTES>>>(lam_p);

    // differential combine -> fp16 ctx
    combine_o<<<(CTX_Q + 255) / 256, 256>>>();

    // output projection + bias (fp32 out)
    gemm_f16<false><<<dim3(DIM_ / TBN, M_ROWS / TBM), 256, GEMM_SMEM_BYTES>>>(
        ctxh, gwoh, bo, out, M_ROWS, DIM_, DIM_);
}